// round 1
// baseline (speedup 1.0000x reference)
#include <cuda_runtime.h>
#include <cuda_bf16.h>
#include <math.h>

#define Bb 64
#define Nn 1024
#define Ff 3
#define Hh 64
#define Ss 32
#define Tt 10

// ---------------- scratch (device globals; no runtime allocation) -------------
__device__ __align__(16) float g_emb[Bb*Nn*Hh];   // h0
__device__ __align__(16) float g_nrm[Bb*Nn*Hh];
__device__ __align__(16) float g_h1 [Bb*Nn*Hh];
__device__ __align__(16) float g_h2 [Bb*Nn*Hh];
__device__ __align__(16) float g_G  [Bb*Tt*Hh*Hh];
__device__ __align__(16) float g_M  [Bb*Tt*Hh*Hh];
__device__ int   g_idx[Bb*Tt*Nn];
__device__ int   g_cnt[Bb*Tt];
__device__ float g_ctx[Bb*Hh];
__device__ float g_state[Bb*Ss];

#define FMA4(A, s, v) { (A).x += (s)*(v).x; (A).y += (s)*(v).y; (A).z += (s)*(v).z; (A).w += (s)*(v).w; }

// ---------------- K1: encoder + L2-normalize ---------------------------------
// grid 1024, block (64,4); each block handles 64 rows (16 iters of 4)
__global__ __launch_bounds__(256) void k_encoder(
    const float* __restrict__ tf, const float* __restrict__ w1,
    const float* __restrict__ b1, const float* __restrict__ w2,
    const float* __restrict__ b2)
{
    __shared__ float s_w2[64*65];
    __shared__ float s_h1[4][64];
    __shared__ float s_red[4][2];
    int j = threadIdx.x, ty = threadIdx.y;
    int tid = ty*64 + j;
    for (int it = 0; it < 16; ++it) {
        int e = tid + it*256;
        s_w2[(e>>6)*65 + (e&63)] = w2[e];
    }
    float w1r0 = w1[j*3+0], w1r1 = w1[j*3+1], w1r2 = w1[j*3+2];
    float bb1 = b1[j], bb2 = b2[j];
    __syncthreads();
    for (int it = 0; it < 16; ++it) {
        int r = blockIdx.x*64 + it*4 + ty;
        const float* f = tf + r*3;
        float h1 = fmaxf(w1r0*f[0] + w1r1*f[1] + w1r2*f[2] + bb1, 0.f);
        s_h1[ty][j] = h1;
        __syncthreads();
        float e = bb2;
        #pragma unroll 16
        for (int k = 0; k < 64; ++k) e += s_h1[ty][k] * s_w2[j*65+k];
        float sq = e*e;
        #pragma unroll
        for (int o = 16; o > 0; o >>= 1) sq += __shfl_xor_sync(0xffffffffu, sq, o);
        if ((j & 31) == 0) s_red[ty][j>>5] = sq;
        __syncthreads();
        float nsum = s_red[ty][0] + s_red[ty][1];
        float inv  = 1.f / fmaxf(sqrtf(nsum), 1e-12f);
        g_emb[r*64 + j] = e;
        g_nrm[r*64 + j] = e * inv;
    }
}

// ---------------- K bucket: per (b,t) index lists ------------------------------
__global__ __launch_bounds__(1024) void k_bucket(const int* __restrict__ types)
{
    __shared__ int scnt[Tt];
    int b = blockIdx.x, n = threadIdx.x;
    if (n < Tt) scnt[n] = 0;
    __syncthreads();
    int t = types[b*Nn + n];
    int pos = atomicAdd(&scnt[t], 1);
    g_idx[(b*Tt + t)*Nn + pos] = n;
    __syncthreads();
    if (n < Tt) g_cnt[b*Tt + n] = scnt[n];
}

// ---------------- K2: G_t = NrmR^T @ HR per (t,b) -----------------------------
// grid (10,64), 256 threads, 4x4 register tile, k-tile = 64 rows
__global__ __launch_bounds__(256) void k_gmat(int layer)
{
    const float* hin = (layer == 0) ? g_emb : g_h1;
    __shared__ __align__(16) float s_A [64*68];
    __shared__ __align__(16) float s_Bh[64*68];
    __shared__ int s_idx[64];
    int t = blockIdx.x, b = blockIdx.y;
    int tid = threadIdx.x;
    int tx = tid & 15, ty = tid >> 4;
    int Kt = g_cnt[b*Tt + t];
    const int* lst = &g_idx[(b*Tt + t)*Nn];
    float4 acc[4];
    #pragma unroll
    for (int i = 0; i < 4; ++i) acc[i] = make_float4(0.f,0.f,0.f,0.f);

    for (int r0 = 0; r0 < Kt; r0 += 64) {
        __syncthreads();
        if (tid < 64) s_idx[tid] = (r0 + tid < Kt) ? lst[r0 + tid] : -1;
        __syncthreads();
        #pragma unroll
        for (int it = 0; it < 16; ++it) {
            int e = tid + it*256;
            int rr = e >> 6, k = e & 63;
            int row = s_idx[rr];
            float av = 0.f, bv = 0.f;
            if (row >= 0) {
                int base = (b*Nn + row)*64 + k;
                av = g_nrm[base];
                bv = hin[base];
            }
            s_A [rr*68 + k] = av;
            s_Bh[rr*68 + k] = bv;
        }
        __syncthreads();
        #pragma unroll 8
        for (int rr = 0; rr < 64; ++rr) {
            float4 a  = *(const float4*)&s_A [rr*68 + ty*4];
            float4 bb = *(const float4*)&s_Bh[rr*68 + tx*4];
            FMA4(acc[0], a.x, bb); FMA4(acc[1], a.y, bb);
            FMA4(acc[2], a.z, bb); FMA4(acc[3], a.w, bb);
        }
    }
    float* Gp = &g_G[(b*Tt + t)*4096];
    #pragma unroll
    for (int i = 0; i < 4; ++i)
        *(float4*)&Gp[(ty*4 + i)*64 + tx*4] = acc[i];
}

// ---------------- K2b: M[b,t'] = sum_t sigmoid(C[t',t]) G[b,t] ----------------
// grid 64, 1024 threads, dyn smem 160KB for all G[b]
__global__ __launch_bounds__(1024) void k_combine(const float* __restrict__ cont)
{
    extern __shared__ __align__(16) float4 s4[];   // 10240 float4
    __shared__ float s_S[Tt*Tt];
    int b = blockIdx.x, tid = threadIdx.x;
    const float4* G4 = (const float4*)g_G + b*10240;
    #pragma unroll
    for (int it = 0; it < 10; ++it) s4[tid + it*1024] = G4[tid + it*1024];
    if (tid < Tt*Tt) s_S[tid] = 1.f / (1.f + expf(-cont[tid]));
    __syncthreads();
    float4* M4 = (float4*)g_M + b*10240;
    #pragma unroll
    for (int tp = 0; tp < Tt; ++tp) {
        float4 o = make_float4(0.f,0.f,0.f,0.f);
        #pragma unroll
        for (int t = 0; t < Tt; ++t) {
            float s = s_S[tp*Tt + t];
            float4 g = s4[t*1024 + tid];
            FMA4(o, s, g);
        }
        M4[tp*1024 + tid] = o;
    }
}

// ---------------- K3: per (t,b): Agg = NrmR @ M ; Hout = relu((HR+Agg)@W^T+b) --
// grid (10,64), 256 threads, dyn smem ~68KB
__global__ __launch_bounds__(256) void k_layer(
    int layer, const float* __restrict__ gnn_w, const float* __restrict__ gnn_b)
{
    const float* hin  = (layer == 0) ? g_emb : g_h1;
    float*       hout = (layer == 0) ? g_h1  : g_h2;
    extern __shared__ __align__(16) float sm[];
    float* s_B  = sm;               // M  [k][c] stride 68
    float* s_B2 = sm + 64*68;       // W^T[k][c] stride 68
    float* s_At = sm + 2*64*68;     // Nrm^T [k][r] stride 68
    float* s_Xt = sm + 3*64*68;     // X^T   [k][r] stride 68
    __shared__ int s_idx[64];
    __shared__ __align__(16) float s_bias[64];

    int t = blockIdx.x, b = blockIdx.y;
    int tid = threadIdx.x;
    int tx = tid & 15, ty = tid >> 4;
    int Kt = g_cnt[b*Tt + t];
    if (Kt == 0) return;

    const float* Mp = &g_M[(b*Tt + t)*4096];
    const float* Wp = gnn_w + layer*4096;
    #pragma unroll
    for (int it = 0; it < 16; ++it) {
        int e = tid + it*256;
        s_B[(e>>6)*68 + (e&63)] = Mp[e];
        int c = e >> 6, k = e & 63;
        s_B2[k*68 + c] = Wp[e];                // transpose of gnn_w
    }
    if (tid < 64) s_bias[tid] = gnn_b[layer*64 + tid];
    const int* lst = &g_idx[(b*Tt + t)*Nn];

    for (int r0 = 0; r0 < Kt; r0 += 64) {
        __syncthreads();
        if (tid < 64) s_idx[tid] = (r0 + tid < Kt) ? lst[r0 + tid] : -1;
        __syncthreads();
        #pragma unroll
        for (int it = 0; it < 16; ++it) {
            int e = tid + it*256;
            int rr = e >> 6, k = e & 63;
            int row = s_idx[rr];
            s_At[k*68 + rr] = (row >= 0) ? g_nrm[(b*Nn + row)*64 + k] : 0.f;
        }
        __syncthreads();

        // GEMM1: Agg[r][c] = sum_k Nrm[r][k] * M[k][c]
        float4 acc[4];
        #pragma unroll
        for (int i = 0; i < 4; ++i) acc[i] = make_float4(0.f,0.f,0.f,0.f);
        #pragma unroll 8
        for (int kk = 0; kk < 64; ++kk) {
            float4 a  = *(const float4*)&s_At[kk*68 + ty*4];
            float4 bb = *(const float4*)&s_B [kk*68 + tx*4];
            FMA4(acc[0], a.x, bb); FMA4(acc[1], a.y, bb);
            FMA4(acc[2], a.z, bb); FMA4(acc[3], a.w, bb);
        }
        // X = H + Agg, write transposed
        #pragma unroll
        for (int i = 0; i < 4; ++i) {
            int row = s_idx[ty*4 + i];
            float4 x = acc[i];
            if (row >= 0) {
                float4 hv = *(const float4*)&hin[(b*Nn + row)*64 + tx*4];
                x.x += hv.x; x.y += hv.y; x.z += hv.z; x.w += hv.w;
            } else {
                x = make_float4(0.f,0.f,0.f,0.f);
            }
            s_Xt[(tx*4+0)*68 + ty*4 + i] = x.x;
            s_Xt[(tx*4+1)*68 + ty*4 + i] = x.y;
            s_Xt[(tx*4+2)*68 + ty*4 + i] = x.z;
            s_Xt[(tx*4+3)*68 + ty*4 + i] = x.w;
        }
        __syncthreads();

        // GEMM2: Out[r][c] = sum_k X[r][k] * W[c][k]
        float4 acc2[4];
        #pragma unroll
        for (int i = 0; i < 4; ++i) acc2[i] = make_float4(0.f,0.f,0.f,0.f);
        #pragma unroll 8
        for (int kk = 0; kk < 64; ++kk) {
            float4 a  = *(const float4*)&s_Xt[kk*68 + ty*4];
            float4 bb = *(const float4*)&s_B2[kk*68 + tx*4];
            FMA4(acc2[0], a.x, bb); FMA4(acc2[1], a.y, bb);
            FMA4(acc2[2], a.z, bb); FMA4(acc2[3], a.w, bb);
        }
        float4 bias = *(const float4*)&s_bias[tx*4];
        #pragma unroll
        for (int i = 0; i < 4; ++i) {
            int row = s_idx[ty*4 + i];
            if (row >= 0) {
                float4 o = acc2[i];
                o.x = fmaxf(o.x + bias.x, 0.f);
                o.y = fmaxf(o.y + bias.y, 0.f);
                o.z = fmaxf(o.z + bias.z, 0.f);
                o.w = fmaxf(o.w + bias.w, 0.f);
                *(float4*)&hout[(b*Nn + row)*64 + tx*4] = o;
            }
        }
    }
}

// ---------------- K4: ctx = mean_n h2 -----------------------------------------
__global__ __launch_bounds__(512) void k_ctx()
{
    __shared__ float s_p[8][64];
    int b = blockIdx.x;
    int d = threadIdx.x, g = threadIdx.y;
    float s = 0.f;
    for (int n = g; n < Nn; n += 8) s += g_h2[(b*Nn + n)*64 + d];
    s_p[g][d] = s;
    __syncthreads();
    if (g == 0) {
        float tot = 0.f;
        #pragma unroll
        for (int i = 0; i < 8; ++i) tot += s_p[i][d];
        g_ctx[b*64 + d] = tot * (1.f/1024.f);
    }
}

// ---------------- K5: GRU ------------------------------------------------------
__global__ __launch_bounds__(96) void k_gru(
    const float* __restrict__ prev, const float* __restrict__ wih,
    const float* __restrict__ whh,  const float* __restrict__ bih,
    const float* __restrict__ bhh,  float* __restrict__ out)
{
    __shared__ float s_gi[96], s_gh[96], s_ctx[64], s_prev[32];
    int b = blockIdx.x, j = threadIdx.x;
    if (j < 64) s_ctx[j]  = g_ctx[b*64 + j];
    if (j < 32) s_prev[j] = prev[b*32 + j];
    __syncthreads();
    float gi = bih[j], gh = bhh[j];
    #pragma unroll 16
    for (int k = 0; k < 64; ++k) gi += s_ctx[k] * wih[j*64 + k];
    #pragma unroll 16
    for (int k = 0; k < 32; ++k) gh += s_prev[k] * whh[j*32 + k];
    s_gi[j] = gi; s_gh[j] = gh;
    __syncthreads();
    if (j < 32) {
        float r  = 1.f / (1.f + expf(-(s_gi[j]      + s_gh[j])));
        float z  = 1.f / (1.f + expf(-(s_gi[32 + j] + s_gh[32 + j])));
        float nn = tanhf(s_gi[64 + j] + r * s_gh[64 + j]);
        float ns = (1.f - z)*nn + z*s_prev[j];
        g_state[b*32 + j] = ns;
        out[Bb*Nn + b*32 + j] = ns;
    }
}

// ---------------- K6: head -----------------------------------------------------
// grid 1024, block (64,4), 64 rows per block
__global__ __launch_bounds__(256) void k_head(
    const float* __restrict__ w1, const float* __restrict__ b1,
    const float* __restrict__ w2, const float* __restrict__ b2,
    float* __restrict__ out)
{
    __shared__ float s_W[96*68];
    __shared__ float s_x[4][96];
    __shared__ float s_red[4][2];
    __shared__ float s_w2[64];
    int j = threadIdx.x, ty = threadIdx.y;
    int tid = ty*64 + j;
    for (int e = tid; e < 64*96; e += 256) {
        int jj = e / 96, k = e % 96;
        s_W[k*68 + jj] = w1[e];
    }
    if (tid < 64) s_w2[tid] = w2[tid];
    float bb = b1[j], b2v = b2[0];
    __syncthreads();
    for (int it = 0; it < 16; ++it) {
        int r = blockIdx.x*64 + it*4 + ty;
        int b = r >> 10;
        s_x[ty][j] = g_h2[r*64 + j];
        if (j < 32) s_x[ty][64 + j] = g_state[b*32 + j];
        __syncthreads();
        float y = bb;
        #pragma unroll 16
        for (int k = 0; k < 96; ++k) y += s_x[ty][k] * s_W[k*68 + j];
        y = fmaxf(y, 0.f) * s_w2[j];
        #pragma unroll
        for (int o = 16; o > 0; o >>= 1) y += __shfl_xor_sync(0xffffffffu, y, o);
        if ((j & 31) == 0) s_red[ty][j>>5] = y;
        __syncthreads();
        if (j == 0) out[r] = s_red[ty][0] + s_red[ty][1] + b2v;
    }
}

// ---------------- launch -------------------------------------------------------
extern "C" void kernel_launch(void* const* d_in, const int* in_sizes, int n_in,
                              void* d_out, int out_size)
{
    const float* tf    = (const float*)d_in[0];
    const int*   types = (const int*)  d_in[1];
    const float* prev  = (const float*)d_in[2];
    const float* ew1   = (const float*)d_in[3];
    const float* eb1   = (const float*)d_in[4];
    const float* ew2   = (const float*)d_in[5];
    const float* eb2   = (const float*)d_in[6];
    const float* cont  = (const float*)d_in[7];
    const float* gw    = (const float*)d_in[8];
    const float* gb    = (const float*)d_in[9];
    const float* wih   = (const float*)d_in[10];
    const float* whh   = (const float*)d_in[11];
    const float* bih   = (const float*)d_in[12];
    const float* bhh   = (const float*)d_in[13];
    const float* hw1   = (const float*)d_in[14];
    const float* hb1   = (const float*)d_in[15];
    const float* hw2   = (const float*)d_in[16];
    const float* hb2   = (const float*)d_in[17];
    float* out = (float*)d_out;

    cudaFuncSetAttribute(k_combine, cudaFuncAttributeMaxDynamicSharedMemorySize, 163840);
    cudaFuncSetAttribute(k_layer,   cudaFuncAttributeMaxDynamicSharedMemorySize, 69632);

    k_encoder<<<1024, dim3(64,4)>>>(tf, ew1, eb1, ew2, eb2);
    k_bucket<<<Bb, 1024>>>(types);
    for (int l = 0; l < 2; ++l) {
        k_gmat   <<<dim3(Tt, Bb), 256>>>(l);
        k_combine<<<Bb, 1024, 163840>>>(cont);
        k_layer  <<<dim3(Tt, Bb), 256, 69632>>>(l, gw, gb);
    }
    k_ctx<<<Bb, dim3(64,8)>>>();
    k_gru<<<Bb, 96>>>(prev, wih, whh, bih, bhh, out);
    k_head<<<1024, dim3(64,4)>>>(hw1, hb1, hw2, hb2, out);
}

// round 2
// speedup vs baseline: 1.7745x; 1.7745x over previous
#include <cuda_runtime.h>
#include <cuda_bf16.h>
#include <math.h>

#define Bb 64
#define Nn 1024
#define Hh 64
#define Ss 32
#define Tt 10

// ---------------- scratch (device globals) ------------------------------------
__device__ __align__(16) float g_emb[Bb*Nn*Hh];
__device__ __align__(16) float g_h1 [Bb*Nn*Hh];
__device__ __align__(16) float g_h2 [Bb*Nn*Hh];
__device__ __align__(16) float g_G  [Bb*Tt*Hh*Hh];
__device__ __align__(16) float g_M  [Bb*Tt*Hh*Hh];
__device__ float g_inv[Bb*Nn];
__device__ int   g_idx[Bb*Tt*Nn];
__device__ int   g_cnt[Bb*Tt];
__device__ float g_ctx[Bb*Hh];
__device__ float g_state[Bb*Ss];

#define FMA4(A, s, v) { (A).x += (s)*(v).x; (A).y += (s)*(v).y; (A).z += (s)*(v).z; (A).w += (s)*(v).w; }

// ---------------- K1: encoder + norm factors ----------------------------------
// grid 1024 (64 rows each), block 256
__global__ __launch_bounds__(256) void k_encoder(
    const float* __restrict__ tf, const float* __restrict__ w1,
    const float* __restrict__ b1, const float* __restrict__ w2,
    const float* __restrict__ b2)
{
    __shared__ __align__(16) float s_h1 [64*68];
    __shared__ __align__(16) float s_w2t[64*68];
    __shared__ __align__(16) float s_f[192];
    __shared__ __align__(16) float s_w1[192];
    __shared__ __align__(16) float s_b1[64];
    __shared__ __align__(16) float s_b2[64];
    int tid = threadIdx.x;
    int tx = tid & 15, ty = tid >> 4;
    int base = blockIdx.x * 64;

    // w2 transposed: s_w2t[k][j] = w2[j*64+k]
    #pragma unroll
    for (int it = 0; it < 16; ++it) {
        int e = tid + it*256;
        int j = e >> 6, k = e & 63;
        s_w2t[k*68 + j] = w2[e];
    }
    if (tid < 192) { s_f[tid] = tf[base*3 + tid]; s_w1[tid] = w1[tid]; }
    if (tid < 64)  { s_b1[tid] = b1[tid]; s_b2[tid] = b2[tid]; }
    __syncthreads();

    // h1 = relu(W1 f + b1) for all 64 rows
    #pragma unroll
    for (int it = 0; it < 16; ++it) {
        int e = tid + it*256;
        int row = e >> 6, k = e & 63;
        float h = s_f[row*3+0]*s_w1[k*3+0] + s_f[row*3+1]*s_w1[k*3+1]
                + s_f[row*3+2]*s_w1[k*3+2] + s_b1[k];
        s_h1[row*68 + k] = fmaxf(h, 0.f);
    }
    __syncthreads();

    // emb = h1 @ W2^T + b2  (4x4 register tile)
    float4 acc[4];
    #pragma unroll
    for (int i = 0; i < 4; ++i) acc[i] = make_float4(0.f,0.f,0.f,0.f);
    #pragma unroll 8
    for (int kk = 0; kk < 64; ++kk) {
        float4 bb = *(const float4*)&s_w2t[kk*68 + tx*4];
        float a0 = s_h1[(ty*4+0)*68 + kk];
        float a1 = s_h1[(ty*4+1)*68 + kk];
        float a2 = s_h1[(ty*4+2)*68 + kk];
        float a3 = s_h1[(ty*4+3)*68 + kk];
        FMA4(acc[0], a0, bb); FMA4(acc[1], a1, bb);
        FMA4(acc[2], a2, bb); FMA4(acc[3], a3, bb);
    }
    float4 bias = *(const float4*)&s_b2[tx*4];
    #pragma unroll
    for (int i = 0; i < 4; ++i) {
        acc[i].x += bias.x; acc[i].y += bias.y;
        acc[i].z += bias.z; acc[i].w += bias.w;
        float sq = acc[i].x*acc[i].x + acc[i].y*acc[i].y
                 + acc[i].z*acc[i].z + acc[i].w*acc[i].w;
        #pragma unroll
        for (int o = 8; o > 0; o >>= 1) sq += __shfl_xor_sync(0xffffffffu, sq, o);
        float inv = 1.f / fmaxf(sqrtf(sq), 1e-12f);
        int r = base + ty*4 + i;
        *(float4*)&g_emb[r*64 + tx*4] = acc[i];
        if (tx == 0) g_inv[r] = inv;
    }
}

// ---------------- K bucket + zero ctx ------------------------------------------
__global__ __launch_bounds__(1024) void k_bucket(const int* __restrict__ types)
{
    __shared__ int scnt[Tt];
    int b = blockIdx.x, n = threadIdx.x;
    if (n < Tt) scnt[n] = 0;
    if (n < 64) g_ctx[b*64 + n] = 0.f;
    __syncthreads();
    int t = types[b*Nn + n];
    int pos = atomicAdd(&scnt[t], 1);
    g_idx[(b*Tt + t)*Nn + pos] = n;
    __syncthreads();
    if (n < Tt) g_cnt[b*Tt + n] = scnt[n];
}

// ---------------- K2: G_t = Nrm^T @ H per (t,b) --------------------------------
__global__ __launch_bounds__(256) void k_gmat(int layer)
{
    const float4* emb4 = (const float4*)g_emb;
    const float4* h4   = (const float4*)((layer == 0) ? g_emb : g_h1);
    __shared__ __align__(16) float s_A [64*68];
    __shared__ __align__(16) float s_Bh[64*68];
    __shared__ int   s_idx[64];
    __shared__ float s_inv[64];
    int t = blockIdx.x, b = blockIdx.y;
    int tid = threadIdx.x;
    int tx = tid & 15, ty = tid >> 4;
    int Kt = g_cnt[b*Tt + t];
    const int* lst = &g_idx[(b*Tt + t)*Nn];
    float4 acc[4];
    #pragma unroll
    for (int i = 0; i < 4; ++i) acc[i] = make_float4(0.f,0.f,0.f,0.f);

    for (int r0 = 0; r0 < Kt; r0 += 64) {
        __syncthreads();
        if (tid < 64) {
            int row = (r0 + tid < Kt) ? lst[r0 + tid] : -1;
            s_idx[tid] = row;
            s_inv[tid] = (row >= 0) ? g_inv[(b<<10) + row] : 0.f;
        }
        __syncthreads();
        #pragma unroll
        for (int it = 0; it < 4; ++it) {
            int e = tid + it*256;
            int rr = e >> 4, kq = e & 15;
            int row = s_idx[rr];
            float4 v = make_float4(0.f,0.f,0.f,0.f);
            float4 w = make_float4(0.f,0.f,0.f,0.f);
            if (row >= 0) {
                int gi = ((b<<10) + row)*16 + kq;
                v = emb4[gi];
                w = (layer == 0) ? v : h4[gi];
            }
            float iv = s_inv[rr];
            *(float4*)&s_Bh[rr*68 + kq*4] = w;
            v.x *= iv; v.y *= iv; v.z *= iv; v.w *= iv;
            *(float4*)&s_A[rr*68 + kq*4] = v;
        }
        __syncthreads();
        #pragma unroll 8
        for (int rr = 0; rr < 64; ++rr) {
            float4 a  = *(const float4*)&s_A [rr*68 + ty*4];
            float4 bb = *(const float4*)&s_Bh[rr*68 + tx*4];
            FMA4(acc[0], a.x, bb); FMA4(acc[1], a.y, bb);
            FMA4(acc[2], a.z, bb); FMA4(acc[3], a.w, bb);
        }
    }
    float* Gp = &g_G[(b*Tt + t)*4096];
    #pragma unroll
    for (int i = 0; i < 4; ++i)
        *(float4*)&Gp[(ty*4 + i)*64 + tx*4] = acc[i];
}

// ---------------- K2b: M[b,tp] = sum_t sigmoid(C) G[b,t] -----------------------
// grid (64,8), 128 threads: each thread one float4 lane, all t in regs
__global__ __launch_bounds__(128) void k_combine(const float* __restrict__ cont)
{
    __shared__ float s_S[Tt*Tt];
    int b = blockIdx.x, tid = threadIdx.x;
    if (tid < Tt*Tt) s_S[tid] = 1.f / (1.f + expf(-cont[tid]));
    __syncthreads();
    int i4 = blockIdx.y * 128 + tid;       // 0..1023 float4 within 64x64
    const float4* G4 = (const float4*)g_G + (size_t)b*10240;
    float4*       M4 = (float4*)g_M       + (size_t)b*10240;
    float4 g[Tt];
    #pragma unroll
    for (int t = 0; t < Tt; ++t) g[t] = G4[t*1024 + i4];
    #pragma unroll
    for (int tp = 0; tp < Tt; ++tp) {
        float4 o = make_float4(0.f,0.f,0.f,0.f);
        #pragma unroll
        for (int t = 0; t < Tt; ++t) {
            float s = s_S[tp*Tt + t];
            FMA4(o, s, g[t]);
        }
        M4[tp*1024 + i4] = o;
    }
}

// ---------------- K3: Agg = Nrm @ M ; Hout = relu((H+Agg)@W^T+b) ---------------
// grid (10,64), 256 threads, dyn smem 69632
__global__ __launch_bounds__(256) void k_layer(
    int layer, const float* __restrict__ gnn_w, const float* __restrict__ gnn_b)
{
    const float* hin  = (layer == 0) ? g_emb : g_h1;
    float*       hout = (layer == 0) ? g_h1  : g_h2;
    const float4* emb4 = (const float4*)g_emb;
    extern __shared__ __align__(16) float sm[];
    float* s_B  = sm;               // M   [k][d] stride 68
    float* s_W  = sm + 64*68;       // W^T [k][c] stride 68
    float* s_A  = sm + 2*64*68;     // nrm [r][k] stride 68
    float* s_X  = sm + 3*64*68;     // X   [r][k] stride 68
    __shared__ int   s_idx[64];
    __shared__ float s_inv[64];
    __shared__ __align__(16) float s_bias[64];
    __shared__ __align__(16) float s_csum[16][64];

    int t = blockIdx.x, b = blockIdx.y;
    int tid = threadIdx.x;
    int tx = tid & 15, ty = tid >> 4;
    int Kt = g_cnt[b*Tt + t];
    if (Kt == 0) return;

    const float* Mp = &g_M[(b*Tt + t)*4096];
    const float* Wp = gnn_w + layer*4096;
    #pragma unroll
    for (int it = 0; it < 16; ++it) {
        int e = tid + it*256;
        int r = e >> 6, c = e & 63;
        s_B[r*68 + c] = Mp[e];        // natural [k][d]
        s_W[c*68 + r] = Wp[e];        // transpose of gnn_w -> [k][c]
    }
    if (tid < 64) s_bias[tid] = gnn_b[layer*64 + tid];
    const int* lst = &g_idx[(b*Tt + t)*Nn];

    float4 psum = make_float4(0.f,0.f,0.f,0.f);

    for (int r0 = 0; r0 < Kt; r0 += 64) {
        __syncthreads();
        if (tid < 64) {
            int row = (r0 + tid < Kt) ? lst[r0 + tid] : -1;
            s_idx[tid] = row;
            s_inv[tid] = (row >= 0) ? g_inv[(b<<10) + row] : 0.f;
        }
        __syncthreads();
        #pragma unroll
        for (int it = 0; it < 4; ++it) {
            int e = tid + it*256;
            int rr = e >> 4, kq = e & 15;
            int row = s_idx[rr];
            float4 v = make_float4(0.f,0.f,0.f,0.f);
            if (row >= 0) v = emb4[((b<<10) + row)*16 + kq];
            float iv = s_inv[rr];
            v.x *= iv; v.y *= iv; v.z *= iv; v.w *= iv;
            *(float4*)&s_A[rr*68 + kq*4] = v;
        }
        __syncthreads();

        // GEMM1: Agg[r][d] = sum_k nrm[r][k] M[k][d]
        float4 acc[4];
        #pragma unroll
        for (int i = 0; i < 4; ++i) acc[i] = make_float4(0.f,0.f,0.f,0.f);
        #pragma unroll 8
        for (int kk = 0; kk < 64; ++kk) {
            float4 bb = *(const float4*)&s_B[kk*68 + tx*4];
            float a0 = s_A[(ty*4+0)*68 + kk];
            float a1 = s_A[(ty*4+1)*68 + kk];
            float a2 = s_A[(ty*4+2)*68 + kk];
            float a3 = s_A[(ty*4+3)*68 + kk];
            FMA4(acc[0], a0, bb); FMA4(acc[1], a1, bb);
            FMA4(acc[2], a2, bb); FMA4(acc[3], a3, bb);
        }
        // X = H + Agg (store natural layout)
        #pragma unroll
        for (int i = 0; i < 4; ++i) {
            int row = s_idx[ty*4 + i];
            float4 x = acc[i];
            if (row >= 0) {
                float4 hv = *(const float4*)&hin[((b<<10) + row)*64 + tx*4];
                x.x += hv.x; x.y += hv.y; x.z += hv.z; x.w += hv.w;
            } else {
                x = make_float4(0.f,0.f,0.f,0.f);
            }
            *(float4*)&s_X[(ty*4+i)*68 + tx*4] = x;
        }
        __syncthreads();

        // GEMM2: Out[r][c] = sum_k X[r][k] W[c][k]
        float4 acc2[4];
        #pragma unroll
        for (int i = 0; i < 4; ++i) acc2[i] = make_float4(0.f,0.f,0.f,0.f);
        #pragma unroll 8
        for (int kk = 0; kk < 64; ++kk) {
            float4 bb = *(const float4*)&s_W[kk*68 + tx*4];
            float a0 = s_X[(ty*4+0)*68 + kk];
            float a1 = s_X[(ty*4+1)*68 + kk];
            float a2 = s_X[(ty*4+2)*68 + kk];
            float a3 = s_X[(ty*4+3)*68 + kk];
            FMA4(acc2[0], a0, bb); FMA4(acc2[1], a1, bb);
            FMA4(acc2[2], a2, bb); FMA4(acc2[3], a3, bb);
        }
        float4 bias = *(const float4*)&s_bias[tx*4];
        #pragma unroll
        for (int i = 0; i < 4; ++i) {
            int row = s_idx[ty*4 + i];
            if (row >= 0) {
                float4 o = acc2[i];
                o.x = fmaxf(o.x + bias.x, 0.f);
                o.y = fmaxf(o.y + bias.y, 0.f);
                o.z = fmaxf(o.z + bias.z, 0.f);
                o.w = fmaxf(o.w + bias.w, 0.f);
                *(float4*)&hout[((b<<10) + row)*64 + tx*4] = o;
                if (layer == 1) { psum.x += o.x; psum.y += o.y; psum.z += o.z; psum.w += o.w; }
            }
        }
    }

    if (layer == 1) {
        *(float4*)&s_csum[ty][tx*4] = psum;
        __syncthreads();
        if (tid < 64) {
            float s = 0.f;
            #pragma unroll
            for (int g = 0; g < 16; ++g) s += s_csum[g][tid];
            atomicAdd(&g_ctx[b*64 + tid], s);
        }
    }
}

// ---------------- K5: GRU -------------------------------------------------------
__global__ __launch_bounds__(96) void k_gru(
    const float* __restrict__ prev, const float* __restrict__ wih,
    const float* __restrict__ whh,  const float* __restrict__ bih,
    const float* __restrict__ bhh,  float* __restrict__ out)
{
    __shared__ float s_gi[96], s_gh[96], s_ctx[64], s_prev[32];
    int b = blockIdx.x, j = threadIdx.x;
    if (j < 64) s_ctx[j]  = g_ctx[b*64 + j] * (1.f/1024.f);
    if (j < 32) s_prev[j] = prev[b*32 + j];
    __syncthreads();
    float gi = bih[j], gh = bhh[j];
    #pragma unroll 16
    for (int k = 0; k < 64; ++k) gi += s_ctx[k] * wih[j*64 + k];
    #pragma unroll 16
    for (int k = 0; k < 32; ++k) gh += s_prev[k] * whh[j*32 + k];
    s_gi[j] = gi; s_gh[j] = gh;
    __syncthreads();
    if (j < 32) {
        float r  = 1.f / (1.f + expf(-(s_gi[j]      + s_gh[j])));
        float z  = 1.f / (1.f + expf(-(s_gi[32 + j] + s_gh[32 + j])));
        float nn = tanhf(s_gi[64 + j] + r * s_gh[64 + j]);
        float ns = (1.f - z)*nn + z*s_prev[j];
        g_state[b*32 + j] = ns;
        out[Bb*Nn + b*32 + j] = ns;
    }
}

// ---------------- K6: head as register-tiled GEMM -------------------------------
// grid 1024 (64 rows each), 256 threads, dyn smem 51712
__global__ __launch_bounds__(256) void k_head(
    const float* __restrict__ w1, const float* __restrict__ b1,
    const float* __restrict__ w2, const float* __restrict__ b2,
    float* __restrict__ out)
{
    extern __shared__ __align__(16) float sm[];
    float* s_X = sm;              // [64][100]  x rows (h2 | state)
    float* s_W = sm + 64*100;     // [96][68]   W1^T
    __shared__ __align__(16) float s_w2[64];
    __shared__ __align__(16) float s_b1[64];
    int tid = threadIdx.x;
    int tx = tid & 15, ty = tid >> 4;
    int base = blockIdx.x * 64;
    int b = blockIdx.x >> 4;

    for (int e = tid; e < 64*96; e += 256) {
        int c = e / 96, k = e - c*96;
        s_W[k*68 + c] = w1[e];
    }
    if (tid < 64) { s_w2[tid] = w2[tid]; s_b1[tid] = b1[tid]; }
    #pragma unroll
    for (int it = 0; it < 16; ++it) {
        int e = tid + it*256;
        int row = e >> 6, k = e & 63;
        s_X[row*100 + k] = g_h2[(base + row)*64 + k];
    }
    #pragma unroll
    for (int it = 0; it < 8; ++it) {
        int e = tid + it*256;
        int row = e >> 5, k = e & 31;
        s_X[row*100 + 64 + k] = g_state[b*32 + k];
    }
    float b2v = b2[0];
    __syncthreads();

    float4 acc[4];
    #pragma unroll
    for (int i = 0; i < 4; ++i) acc[i] = make_float4(0.f,0.f,0.f,0.f);
    #pragma unroll 8
    for (int kk = 0; kk < 96; ++kk) {
        float4 bb = *(const float4*)&s_W[kk*68 + tx*4];
        float a0 = s_X[(ty*4+0)*100 + kk];
        float a1 = s_X[(ty*4+1)*100 + kk];
        float a2 = s_X[(ty*4+2)*100 + kk];
        float a3 = s_X[(ty*4+3)*100 + kk];
        FMA4(acc[0], a0, bb); FMA4(acc[1], a1, bb);
        FMA4(acc[2], a2, bb); FMA4(acc[3], a3, bb);
    }
    float4 bias = *(const float4*)&s_b1[tx*4];
    float4 w2v  = *(const float4*)&s_w2[tx*4];
    #pragma unroll
    for (int i = 0; i < 4; ++i) {
        float y = fmaxf(acc[i].x + bias.x, 0.f)*w2v.x
                + fmaxf(acc[i].y + bias.y, 0.f)*w2v.y
                + fmaxf(acc[i].z + bias.z, 0.f)*w2v.z
                + fmaxf(acc[i].w + bias.w, 0.f)*w2v.w;
        #pragma unroll
        for (int o = 8; o > 0; o >>= 1) y += __shfl_xor_sync(0xffffffffu, y, o);
        if (tx == 0) out[base + ty*4 + i] = y + b2v;
    }
}

// ---------------- launch ---------------------------------------------------------
extern "C" void kernel_launch(void* const* d_in, const int* in_sizes, int n_in,
                              void* d_out, int out_size)
{
    const float* tf    = (const float*)d_in[0];
    const int*   types = (const int*)  d_in[1];
    const float* prev  = (const float*)d_in[2];
    const float* ew1   = (const float*)d_in[3];
    const float* eb1   = (const float*)d_in[4];
    const float* ew2   = (const float*)d_in[5];
    const float* eb2   = (const float*)d_in[6];
    const float* cont  = (const float*)d_in[7];
    const float* gw    = (const float*)d_in[8];
    const float* gb    = (const float*)d_in[9];
    const float* wih   = (const float*)d_in[10];
    const float* whh   = (const float*)d_in[11];
    const float* bih   = (const float*)d_in[12];
    const float* bhh   = (const float*)d_in[13];
    const float* hw1   = (const float*)d_in[14];
    const float* hb1   = (const float*)d_in[15];
    const float* hw2   = (const float*)d_in[16];
    const float* hb2   = (const float*)d_in[17];
    float* out = (float*)d_out;

    cudaFuncSetAttribute(k_layer, cudaFuncAttributeMaxDynamicSharedMemorySize, 69632);
    cudaFuncSetAttribute(k_head,  cudaFuncAttributeMaxDynamicSharedMemorySize, 51712);

    k_encoder<<<1024, 256>>>(tf, ew1, eb1, ew2, eb2);
    k_bucket<<<Bb, 1024>>>(types);
    for (int l = 0; l < 2; ++l) {
        k_gmat   <<<dim3(Tt, Bb), 256>>>(l);
        k_combine<<<dim3(Bb, 8), 128>>>(cont);
        k_layer  <<<dim3(Tt, Bb), 256, 69632>>>(l, gw, gb);
    }
    k_gru<<<Bb, 96>>>(prev, wih, whh, bih, bhh, out);
    k_head<<<1024, 256, 51712>>>(hw1, hb1, hw2, hb2, out);
}